// round 4
// baseline (speedup 1.0000x reference)
#include <cuda_runtime.h>
#include <cstdint>

// B=16384, N=64, D=64, O=64
// softmax(others@a2 + robot@a1) == softmax(others@a2)  (robot term constant)
// out = elu( diag(1,attn) @ (h@W) )   -- attn folded into EPILOGUE (attn>0)
// Fully fused: GEMM computes h@W unscaled; dot-partials (h·v2) are accumulated
// from the raw A-fragment loads inside the GEMM loop; softmax is warp-local
// (shfl only). ONE __syncthreads per batch (buffer management only).

#define GB 8      // batches per CTA
#define HS 68     // h smem row stride (floats): conflict-free A-frag loads

__device__ __forceinline__ unsigned f2tf32(float x) {
    unsigned r;
    asm("cvt.rna.tf32.f32 %0, %1;" : "=r"(r) : "f"(x));
    return r;
}

__device__ __forceinline__ float elu1(float x) {
    return x > 0.f ? x : expm1f(x);
}

__device__ __forceinline__ void cp_async16(uint32_t saddr, const void* gptr) {
    asm volatile("cp.async.cg.shared.global [%0], [%1], 16;\n"
                 :: "r"(saddr), "l"(gptr));
}

__global__ __launch_bounds__(128, 5)
void gat_fused_kernel(const float* __restrict__ h,
                      const float* __restrict__ W,
                      const float* __restrict__ a,
                      float* __restrict__ out) {
    __shared__ float sh[2][64 * HS];   // double-buffered h (fp32)
    __shared__ float sv2[64];

    const int tid  = threadIdx.x;
    const int lane = tid & 31;
    const int warp = tid >> 5;
    const int gid  = lane >> 2;   // 0..7
    const int tig  = lane & 3;    // 0..3

    // ---- W B-fragments into registers (once). warp w: cols [16w, 16w+16) ----
    unsigned bfr[8][2][2];
    {
        const int n0 = warp * 16 + gid;
#pragma unroll
        for (int kk = 0; kk < 8; ++kk)
#pragma unroll
            for (int nt = 0; nt < 2; ++nt) {
                int col = n0 + nt * 8;
                bfr[kk][nt][0] = f2tf32(W[(kk * 8 + tig) * 64 + col]);
                bfr[kk][nt][1] = f2tf32(W[(kk * 8 + tig + 4) * 64 + col]);
            }
    }

    // ---- v2 = W @ a2 (per CTA; threads 0..63) ----
    if (tid < 64) {
        const float* a2 = a + 64;
        float s = 0.f;
#pragma unroll
        for (int o = 0; o < 64; ++o) s = fmaf(W[tid * 64 + o], a2[o], s);
        sv2[tid] = s;
    }

    const size_t base = (size_t)blockIdx.x * GB * 4096;

    // ---- prefetch batch 0 ----
    {
        const float* hb = h + base;
        uint32_t sb = (uint32_t)__cvta_generic_to_shared(&sh[0][0]);
#pragma unroll
        for (int c = tid; c < 1024; c += 128) {
            int row = c >> 4, q = c & 15;
            cp_async16(sb + (row * HS + q * 4) * 4, hb + c * 4);
        }
        asm volatile("cp.async.commit_group;\n");
    }

    for (int g = 0; g < GB; ++g) {
        const int buf = g & 1;

        asm volatile("cp.async.wait_group 0;\n");
        __syncthreads();   // buf[g] visible; all warps done with buf[g-1]; sv2 ready

        // ---- prefetch batch g+1 ----
        if (g + 1 < GB) {
            const float* hb = h + base + (size_t)(g + 1) * 4096;
            uint32_t sb = (uint32_t)__cvta_generic_to_shared(&sh[buf ^ 1][0]);
#pragma unroll
            for (int c = tid; c < 1024; c += 128) {
                int row = c >> 4, q = c & 15;
                cp_async16(sb + (row * HS + q * 4) * 4, hb + c * 4);
            }
            asm volatile("cp.async.commit_group;\n");
        }

        // ---- fused GEMM (unscaled) + dot partials ----
        float acc[4][2][4];
#pragma unroll
        for (int mt = 0; mt < 4; ++mt)
#pragma unroll
            for (int nt = 0; nt < 2; ++nt)
#pragma unroll
                for (int k = 0; k < 4; ++k) acc[mt][nt][k] = 0.f;

        float pd[4][2];    // pd[mt][0]: row gid+16mt ; pd[mt][1]: row gid+16mt+8
#pragma unroll
        for (int mt = 0; mt < 4; ++mt) { pd[mt][0] = 0.f; pd[mt][1] = 0.f; }

        const float* shb = &sh[buf][0];
#pragma unroll
        for (int kk = 0; kk < 8; ++kk) {
            const int c = kk * 8 + tig;
            const float v2c  = sv2[c];
            const float v2c4 = sv2[c + 4];
#pragma unroll
            for (int mt = 0; mt < 4; ++mt) {
                const int r0 = mt * 16 + gid;
                float a0f = shb[r0 * HS + c];
                float a1f = shb[(r0 + 8) * HS + c];
                float a2f = shb[r0 * HS + c + 4];
                float a3f = shb[(r0 + 8) * HS + c + 4];

                pd[mt][0] = fmaf(a0f, v2c, fmaf(a2f, v2c4, pd[mt][0]));
                pd[mt][1] = fmaf(a1f, v2c, fmaf(a3f, v2c4, pd[mt][1]));

                unsigned a0 = f2tf32(a0f), a1 = f2tf32(a1f);
                unsigned a2 = f2tf32(a2f), a3 = f2tf32(a3f);
#pragma unroll
                for (int nt = 0; nt < 2; ++nt) {
                    asm volatile(
                        "mma.sync.aligned.m16n8k8.row.col.f32.tf32.tf32.f32 "
                        "{%0,%1,%2,%3}, {%4,%5,%6,%7}, {%8,%9}, {%0,%1,%2,%3};"
                        : "+f"(acc[mt][nt][0]), "+f"(acc[mt][nt][1]),
                          "+f"(acc[mt][nt][2]), "+f"(acc[mt][nt][3])
                        : "r"(a0), "r"(a1), "r"(a2), "r"(a3),
                          "r"(bfr[kk][nt][0]), "r"(bfr[kk][nt][1]));
                }
            }
        }

        // ---- warp-local softmax over rows 1..63 ----
        // reduce pd over the 4 tig lanes (masks 1,2); every lane keeps the sum
        float d[8];
#pragma unroll
        for (int mt = 0; mt < 4; ++mt)
#pragma unroll
            for (int b2 = 0; b2 < 2; ++b2) {
                float s = pd[mt][b2];
                s += __shfl_xor_sync(0xffffffffu, s, 1);
                s += __shfl_xor_sync(0xffffffffu, s, 2);
                d[2 * mt + b2] = s;   // row gid + 8*(2mt+b2)
            }
        if (gid == 0) d[0] = -1e30f;  // robot row excluded from softmax

        float m = d[0];
#pragma unroll
        for (int j = 1; j < 8; ++j) m = fmaxf(m, d[j]);
        m = fmaxf(m, __shfl_xor_sync(0xffffffffu, m, 4));
        m = fmaxf(m, __shfl_xor_sync(0xffffffffu, m, 8));
        m = fmaxf(m, __shfl_xor_sync(0xffffffffu, m, 16));

        float e[8], s = 0.f;
#pragma unroll
        for (int j = 0; j < 8; ++j) { e[j] = __expf(d[j] - m); s += e[j]; }
        s += __shfl_xor_sync(0xffffffffu, s, 4);
        s += __shfl_xor_sync(0xffffffffu, s, 8);
        s += __shfl_xor_sync(0xffffffffu, s, 16);
        const float inv = 1.f / s;

        float f[8];
#pragma unroll
        for (int j = 0; j < 8; ++j) f[j] = e[j] * inv;
        if (gid == 0) f[0] = 1.f;     // robot row passes through unscaled

        // ---- epilogue: scale, elu, store ----
        float* ob = out + base + (size_t)g * 4096;
#pragma unroll
        for (int mt = 0; mt < 4; ++mt) {
            const int rA = mt * 16 + gid;
            const int rB = rA + 8;
            const float fA = f[2 * mt], fB = f[2 * mt + 1];
#pragma unroll
            for (int nt = 0; nt < 2; ++nt) {
                int col = warp * 16 + nt * 8 + tig * 2;
                float2 v0 = make_float2(elu1(acc[mt][nt][0] * fA),
                                        elu1(acc[mt][nt][1] * fA));
                float2 v1 = make_float2(elu1(acc[mt][nt][2] * fB),
                                        elu1(acc[mt][nt][3] * fB));
                *reinterpret_cast<float2*>(ob + rA * 64 + col) = v0;
                *reinterpret_cast<float2*>(ob + rB * 64 + col) = v1;
            }
        }
    }
}

extern "C" void kernel_launch(void* const* d_in, const int* in_sizes, int n_in,
                              void* d_out, int out_size) {
    const float* h = (const float*)d_in[0];   // (16384, 64, 64) f32
    const float* W = (const float*)d_in[1];   // (64, 64) f32
    const float* a = (const float*)d_in[2];   // (128, 1) f32
    float* out = (float*)d_out;               // (16384, 64, 64) f32

    gat_fused_kernel<<<16384 / GB, 128>>>(h, W, a, out);
}

// round 5
// speedup vs baseline: 1.2061x; 1.2061x over previous
#include <cuda_runtime.h>
#include <cstdint>

// B=16384, N=64, D=64, O=64
// softmax(others@a2 + robot@a1) == softmax(others@a2)  (robot term constant)
// out = elu( diag(1,attn) @ (h@W) )   -- attn folded into the epilogue
// 256-thread CTA, 8 warps per batch: warp w -> rows [16*(w&3),+16) x cols
// [32*(w>>2),+32). B-fragments in registers (loaded once). Dot-partials fused
// into A-fragment loads; dots exchanged via smem; softmax warp-local.

#define GB 8      // batches per CTA
#define HS 68     // h smem row stride (floats): conflict-free A-frag loads

__device__ __forceinline__ unsigned f2tf32(float x) {
    unsigned r;
    asm("cvt.rna.tf32.f32 %0, %1;" : "=r"(r) : "f"(x));
    return r;
}

// fast elu: abs err ~1e-7 vs expm1f -- invisible at rel_err 3e-4 scale
__device__ __forceinline__ float elu1(float x) {
    return x > 0.f ? x : (__expf(x) - 1.f);
}

__device__ __forceinline__ void cp_async16(uint32_t saddr, const void* gptr) {
    asm volatile("cp.async.cg.shared.global [%0], [%1], 16;\n"
                 :: "r"(saddr), "l"(gptr));
}

__global__ __launch_bounds__(256)
void gat_fused_kernel(const float* __restrict__ h,
                      const float* __restrict__ W,
                      const float* __restrict__ a,
                      float* __restrict__ out) {
    __shared__ float sh[2][64 * HS];   // double-buffered h (fp32)
    __shared__ float sdots[64];
    __shared__ float sv2[64];

    const int tid  = threadIdx.x;
    const int lane = tid & 31;
    const int warp = tid >> 5;
    const int gid  = lane >> 2;    // 0..7
    const int tig  = lane & 3;     // 0..3
    const int m0   = warp & 3;     // m-tile: rows [16*m0, +16)
    const int cg   = warp >> 2;    // col group: cols [32*cg, +32)

    // ---- B-fragments into registers (once): 8 kk x 4 nt x 2 ----
    unsigned bfr[8][4][2];
    {
        const int colb = cg * 32 + gid;
#pragma unroll
        for (int kk = 0; kk < 8; ++kk)
#pragma unroll
            for (int nt = 0; nt < 4; ++nt) {
                int col = colb + nt * 8;
                bfr[kk][nt][0] = f2tf32(W[(kk * 8 + tig) * 64 + col]);
                bfr[kk][nt][1] = f2tf32(W[(kk * 8 + tig + 4) * 64 + col]);
            }
    }

    // ---- v2 = W @ a2 (threads 0..63) ----
    if (tid < 64) {
        const float* a2 = a + 64;
        float s = 0.f;
#pragma unroll
        for (int o = 0; o < 64; ++o) s = fmaf(W[tid * 64 + o], a2[o], s);
        sv2[tid] = s;
    }

    const size_t base = (size_t)blockIdx.x * GB * 4096;

    // ---- prefetch batch 0 ----
    {
        const float* hb = h + base;
        uint32_t sb = (uint32_t)__cvta_generic_to_shared(&sh[0][0]);
#pragma unroll
        for (int c = tid; c < 1024; c += 256) {
            int row = c >> 4, q = c & 15;
            cp_async16(sb + (row * HS + q * 4) * 4, hb + c * 4);
        }
        asm volatile("cp.async.commit_group;\n");
    }

    const int rA = m0 * 16 + gid;   // this thread's two output rows
    const int rB = rA + 8;

    for (int g = 0; g < GB; ++g) {
        const int buf = g & 1;

        asm volatile("cp.async.wait_group 0;\n");
        __syncthreads();   // bar A: buf[g] ready; prev iter's sdots reads done

        // ---- prefetch batch g+1 ----
        if (g + 1 < GB) {
            const float* hb = h + base + (size_t)(g + 1) * 4096;
            uint32_t sb = (uint32_t)__cvta_generic_to_shared(&sh[buf ^ 1][0]);
#pragma unroll
            for (int c = tid; c < 1024; c += 256) {
                int row = c >> 4, q = c & 15;
                cp_async16(sb + (row * HS + q * 4) * 4, hb + c * 4);
            }
            asm volatile("cp.async.commit_group;\n");
        }

        // ---- GEMM (unscaled) + dot partials ----
        float acc[4][4];
#pragma unroll
        for (int nt = 0; nt < 4; ++nt)
#pragma unroll
            for (int k = 0; k < 4; ++k) acc[nt][k] = 0.f;

        float pd0 = 0.f, pd1 = 0.f;
        const float* shb = &sh[buf][0];

#pragma unroll
        for (int kk = 0; kk < 8; ++kk) {
            const int c = kk * 8 + tig;
            float a0f = shb[rA * HS + c];
            float a1f = shb[rB * HS + c];
            float a2f = shb[rA * HS + c + 4];
            float a3f = shb[rB * HS + c + 4];

            const float v2c  = sv2[c];
            const float v2c4 = sv2[c + 4];
            pd0 = fmaf(a0f, v2c, fmaf(a2f, v2c4, pd0));
            pd1 = fmaf(a1f, v2c, fmaf(a3f, v2c4, pd1));

            unsigned a0 = f2tf32(a0f), a1 = f2tf32(a1f);
            unsigned a2 = f2tf32(a2f), a3 = f2tf32(a3f);
#pragma unroll
            for (int nt = 0; nt < 4; ++nt) {
                asm volatile(
                    "mma.sync.aligned.m16n8k8.row.col.f32.tf32.tf32.f32 "
                    "{%0,%1,%2,%3}, {%4,%5,%6,%7}, {%8,%9}, {%0,%1,%2,%3};"
                    : "+f"(acc[nt][0]), "+f"(acc[nt][1]),
                      "+f"(acc[nt][2]), "+f"(acc[nt][3])
                    : "r"(a0), "r"(a1), "r"(a2), "r"(a3),
                      "r"(bfr[kk][nt][0]), "r"(bfr[kk][nt][1]));
            }
        }

        // ---- reduce dots over tig lanes; publish to smem (col-group 0 only) ----
        pd0 += __shfl_xor_sync(0xffffffffu, pd0, 1);
        pd0 += __shfl_xor_sync(0xffffffffu, pd0, 2);
        pd1 += __shfl_xor_sync(0xffffffffu, pd1, 1);
        pd1 += __shfl_xor_sync(0xffffffffu, pd1, 2);
        if (cg == 0 && tig == 0) {
            sdots[rA] = pd0;
            sdots[rB] = pd1;
        }
        __syncthreads();   // bar B: sdots complete

        // ---- warp-local softmax over rows 1..63 ----
        float x0 = (lane >= 1) ? sdots[lane] : -1e30f;
        float x1 = sdots[lane + 32];
        float m = fmaxf(x0, x1);
#pragma unroll
        for (int off = 16; off; off >>= 1)
            m = fmaxf(m, __shfl_xor_sync(0xffffffffu, m, off));
        float e0 = (lane >= 1) ? __expf(x0 - m) : 0.f;
        float e1 = __expf(x1 - m);
        float s = e0 + e1;
#pragma unroll
        for (int off = 16; off; off >>= 1)
            s += __shfl_xor_sync(0xffffffffu, s, off);
        const float inv = 1.f / s;

        // factors for this thread's two rows (dots already in pd0/pd1)
        const float fA = (rA == 0) ? 1.f : __expf(pd0 - m) * inv;
        const float fB = __expf(pd1 - m) * inv;   // rB >= 8, never robot

        // ---- epilogue: scale, elu, store ----
        float* ob = out + base + (size_t)g * 4096;
#pragma unroll
        for (int nt = 0; nt < 4; ++nt) {
            int col = cg * 32 + nt * 8 + tig * 2;
            float2 v0 = make_float2(elu1(acc[nt][0] * fA), elu1(acc[nt][1] * fA));
            float2 v1 = make_float2(elu1(acc[nt][2] * fB), elu1(acc[nt][3] * fB));
            *reinterpret_cast<float2*>(ob + rA * 64 + col) = v0;
            *reinterpret_cast<float2*>(ob + rB * 64 + col) = v1;
        }
    }
}

extern "C" void kernel_launch(void* const* d_in, const int* in_sizes, int n_in,
                              void* d_out, int out_size) {
    const float* h = (const float*)d_in[0];   // (16384, 64, 64) f32
    const float* W = (const float*)d_in[1];   // (64, 64) f32
    const float* a = (const float*)d_in[2];   // (128, 1) f32
    float* out = (float*)d_out;               // (16384, 64, 64) f32

    gat_fused_kernel<<<16384 / GB, 256>>>(h, W, a, out);
}

// round 6
// speedup vs baseline: 1.2388x; 1.0271x over previous
#include <cuda_runtime.h>
#include <cstdint>

// B=16384, N=64, D=64, O=64
// softmax(others@a2 + robot@a1) == softmax(others@a2)  (robot term constant)
// out = elu( diag(1,attn) @ (h@W) )   -- attn folded into the epilogue
// 256-thread CTA, warp w -> rows [16*(w&3),+16) x cols [32*(w>>2),+32).
// K-permuted so A-fragments load as LDS.128; N-permuted so stores are STG.128.
// B-fragments in registers (once). Dots fused into A loads; softmax warp-local.

#define GB 8      // batches per CTA
#define HS 80     // h smem row stride (floats): 80 % 32 == 16 -> conflict-free f4

__device__ __forceinline__ unsigned f2tf32(float x) {
    unsigned r;
    asm("cvt.rna.tf32.f32 %0, %1;" : "=r"(r) : "f"(x));
    return r;
}

__device__ __forceinline__ float elu1(float x) {
    return x > 0.f ? x : (__expf(x) - 1.f);
}

__device__ __forceinline__ void cp_async16(uint32_t saddr, const void* gptr) {
    asm volatile("cp.async.cg.shared.global [%0], [%1], 16;\n"
                 :: "r"(saddr), "l"(gptr));
}

__global__ __launch_bounds__(256)
void gat_fused_kernel(const float* __restrict__ h,
                      const float* __restrict__ W,
                      const float* __restrict__ a,
                      float* __restrict__ out) {
    __shared__ float sh[2][64 * HS];            // double-buffered h (fp32)
    __shared__ float sdots[64];
    __shared__ __align__(16) float sv2[64];

    const int tid  = threadIdx.x;
    const int lane = tid & 31;
    const int warp = tid >> 5;
    const int gid  = lane >> 2;    // 0..7
    const int tig  = lane & 3;     // 0..3
    const int m0   = warp & 3;     // m-tile: rows [16*m0, +16)
    const int cg   = warp >> 2;    // col group: cols [32*cg, +32)

    // ---- B-fragments into registers (once), with K- and N-permutation ----
    // K-perm: slab s (s=2q+odd): k_pos t   -> W row 16q + 4t + 2*odd
    //                            k_pos t+4 -> W row 16q + 4t + 2*odd + 1
    // N-perm: tile nt, tile-local n -> col cg*32+(nt>>1)*16+(n>>1)*4+(nt&1)*2+(n&1)
    unsigned bfr[8][4][2];
    {
#pragma unroll
        for (int s = 0; s < 8; ++s) {
            const int q = s >> 1, odd = s & 1;
            const int kr0 = 16 * q + 4 * tig + 2 * odd;   // k_pos = tig
            const int kr1 = kr0 + 1;                      // k_pos = tig+4
#pragma unroll
            for (int nt = 0; nt < 4; ++nt) {
                int col = cg * 32 + (nt >> 1) * 16 + (gid >> 1) * 4
                        + (nt & 1) * 2 + (gid & 1);
                bfr[s][nt][0] = f2tf32(W[kr0 * 64 + col]);
                bfr[s][nt][1] = f2tf32(W[kr1 * 64 + col]);
            }
        }
    }

    // ---- v2 = W @ a2 (threads 0..63) ----
    if (tid < 64) {
        const float* a2 = a + 64;
        float s = 0.f;
#pragma unroll
        for (int o = 0; o < 64; ++o) s = fmaf(W[tid * 64 + o], a2[o], s);
        sv2[tid] = s;
    }

    const size_t base = (size_t)blockIdx.x * GB * 4096;

    // ---- prefetch batch 0 ----
    {
        const float* hb = h + base;
        uint32_t sb = (uint32_t)__cvta_generic_to_shared(&sh[0][0]);
#pragma unroll
        for (int c = tid; c < 1024; c += 256) {
            int row = c >> 4, q = c & 15;
            cp_async16(sb + (row * HS + q * 4) * 4, hb + c * 4);
        }
        asm volatile("cp.async.commit_group;\n");
    }

    const int rA = m0 * 16 + gid;   // this thread's two output rows
    const int rB = rA + 8;

    for (int g = 0; g < GB; ++g) {
        const int buf = g & 1;

        asm volatile("cp.async.wait_group 0;\n");
        __syncthreads();   // buf[g] ready; prev iter's sdots reads done; sv2 ready

        // ---- prefetch batch g+1 ----
        if (g + 1 < GB) {
            const float* hb = h + base + (size_t)(g + 1) * 4096;
            uint32_t sb = (uint32_t)__cvta_generic_to_shared(&sh[buf ^ 1][0]);
#pragma unroll
            for (int c = tid; c < 1024; c += 256) {
                int row = c >> 4, q = c & 15;
                cp_async16(sb + (row * HS + q * 4) * 4, hb + c * 4);
            }
            asm volatile("cp.async.commit_group;\n");
        }

        // ---- GEMM (unscaled) + dot partials, K-permuted float4 loads ----
        float acc[4][4];
#pragma unroll
        for (int nt = 0; nt < 4; ++nt)
#pragma unroll
            for (int k = 0; k < 4; ++k) acc[nt][k] = 0.f;

        float pd0 = 0.f, pd1 = 0.f;
        const float* shb = &sh[buf][0];

#pragma unroll
        for (int q = 0; q < 4; ++q) {
            const int cb = 16 * q + 4 * tig;
            const float4 vA = *reinterpret_cast<const float4*>(&shb[rA * HS + cb]);
            const float4 vB = *reinterpret_cast<const float4*>(&shb[rB * HS + cb]);
            const float4 vv = *reinterpret_cast<const float4*>(&sv2[cb]);

            pd0 = fmaf(vA.x, vv.x, fmaf(vA.y, vv.y,
                  fmaf(vA.z, vv.z, fmaf(vA.w, vv.w, pd0))));
            pd1 = fmaf(vB.x, vv.x, fmaf(vB.y, vv.y,
                  fmaf(vB.z, vv.z, fmaf(vB.w, vv.w, pd1))));

            // slab 2q   : a0=vA.x a1=vB.x a2=vA.y a3=vB.y
            // slab 2q+1 : a0=vA.z a1=vB.z a2=vA.w a3=vB.w
            unsigned e0 = f2tf32(vA.x), e1 = f2tf32(vB.x);
            unsigned e2 = f2tf32(vA.y), e3 = f2tf32(vB.y);
            unsigned o0 = f2tf32(vA.z), o1 = f2tf32(vB.z);
            unsigned o2 = f2tf32(vA.w), o3 = f2tf32(vB.w);
#pragma unroll
            for (int nt = 0; nt < 4; ++nt) {
                asm volatile(
                    "mma.sync.aligned.m16n8k8.row.col.f32.tf32.tf32.f32 "
                    "{%0,%1,%2,%3}, {%4,%5,%6,%7}, {%8,%9}, {%0,%1,%2,%3};"
                    : "+f"(acc[nt][0]), "+f"(acc[nt][1]),
                      "+f"(acc[nt][2]), "+f"(acc[nt][3])
                    : "r"(e0), "r"(e1), "r"(e2), "r"(e3),
                      "r"(bfr[2 * q][nt][0]), "r"(bfr[2 * q][nt][1]));
            }
#pragma unroll
            for (int nt = 0; nt < 4; ++nt) {
                asm volatile(
                    "mma.sync.aligned.m16n8k8.row.col.f32.tf32.tf32.f32 "
                    "{%0,%1,%2,%3}, {%4,%5,%6,%7}, {%8,%9}, {%0,%1,%2,%3};"
                    : "+f"(acc[nt][0]), "+f"(acc[nt][1]),
                      "+f"(acc[nt][2]), "+f"(acc[nt][3])
                    : "r"(o0), "r"(o1), "r"(o2), "r"(o3),
                      "r"(bfr[2 * q + 1][nt][0]), "r"(bfr[2 * q + 1][nt][1]));
            }
        }

        // ---- reduce dots over tig lanes; publish (col-group 0 only) ----
        pd0 += __shfl_xor_sync(0xffffffffu, pd0, 1);
        pd0 += __shfl_xor_sync(0xffffffffu, pd0, 2);
        pd1 += __shfl_xor_sync(0xffffffffu, pd1, 1);
        pd1 += __shfl_xor_sync(0xffffffffu, pd1, 2);
        if (cg == 0 && tig == 0) {
            sdots[rA] = pd0;
            sdots[rB] = pd1;
        }
        __syncthreads();   // sdots complete

        // ---- warp-local softmax over rows 1..63 ----
        float x0 = (lane >= 1) ? sdots[lane] : -1e30f;
        float x1 = sdots[lane + 32];
        float m = fmaxf(x0, x1);
#pragma unroll
        for (int off = 16; off; off >>= 1)
            m = fmaxf(m, __shfl_xor_sync(0xffffffffu, m, off));
        float e0s = (lane >= 1) ? __expf(x0 - m) : 0.f;
        float e1s = __expf(x1 - m);
        float s = e0s + e1s;
#pragma unroll
        for (int off = 16; off; off >>= 1)
            s += __shfl_xor_sync(0xffffffffu, s, off);
        const float inv = 1.f / s;

        const float fA = (rA == 0) ? 1.f : __expf(pd0 - m) * inv;
        const float fB = __expf(pd1 - m) * inv;   // rB >= 8, never robot

        // ---- epilogue: scale, elu, STG.128 (N-permutation makes cols contiguous) ----
        float* ob = out + base + (size_t)g * 4096;
#pragma unroll
        for (int p = 0; p < 2; ++p) {
            const int col = cg * 32 + p * 16 + tig * 4;
            float4 v0 = make_float4(elu1(acc[2 * p][0] * fA),
                                    elu1(acc[2 * p][1] * fA),
                                    elu1(acc[2 * p + 1][0] * fA),
                                    elu1(acc[2 * p + 1][1] * fA));
            float4 v1 = make_float4(elu1(acc[2 * p][2] * fB),
                                    elu1(acc[2 * p][3] * fB),
                                    elu1(acc[2 * p + 1][2] * fB),
                                    elu1(acc[2 * p + 1][3] * fB));
            *reinterpret_cast<float4*>(ob + rA * 64 + col) = v0;
            *reinterpret_cast<float4*>(ob + rB * 64 + col) = v1;
        }
    }
}

extern "C" void kernel_launch(void* const* d_in, const int* in_sizes, int n_in,
                              void* d_out, int out_size) {
    const float* h = (const float*)d_in[0];   // (16384, 64, 64) f32
    const float* W = (const float*)d_in[1];   // (64, 64) f32
    const float* a = (const float*)d_in[2];   // (128, 1) f32
    float* out = (float*)d_out;               // (16384, 64, 64) f32

    gat_fused_kernel<<<16384 / GB, 256>>>(h, W, a, out);
}